// round 17
// baseline (speedup 1.0000x reference)
#include <cuda_runtime.h>
#include <math.h>
#include <stdint.h>

// Problem shape (fixed): x [8, 128, 512, 512] f32, conv_w [16,1,3,3], conv_b [16]
// out [8, 1, 512, 512] f32 with per-tile reassembly layout:
//   out_flat = b*HW + seg*16384 + r*128 + c, seg = ti*4 + tj
#define Bb   8
#define Cc   128
#define Hh   512
#define Ww   512
#define HW   (Hh * Ww)        /* 262144 */
#define CHW  (Cc * HW)
#define TS   128              /* tile side */
#define NSEG 16

__device__ __forceinline__ uint32_t smem_u32(const void* p) {
    return (uint32_t)__cvta_generic_to_shared(p);
}

__device__ __forceinline__ void mbar_init(uint32_t a, int cnt) {
    asm volatile("mbarrier.init.shared.b64 [%0], %1;" :: "r"(a), "r"(cnt) : "memory");
}

__device__ __forceinline__ void mbar_arrive(uint32_t a) {
    asm volatile("mbarrier.arrive.release.cta.shared::cta.b64 _, [%0];" :: "r"(a) : "memory");
}

__device__ __forceinline__ void mbar_wait_p0(uint32_t a) {
    uint32_t done = 0;
    while (!done) {
        asm volatile(
            "{\n\t.reg .pred p;\n\t"
            "mbarrier.try_wait.parity.acquire.cta.shared::cta.b64 p, [%1], 0;\n\t"
            "selp.b32 %0, 1, 0, p;\n\t}"
            : "=r"(done) : "r"(a) : "memory");
    }
}

// Fused kernel, wide-burst variant: one block = 8-row x 256-col strip spanning
// TWO adjacent segments (tj pair) -> each warp reads 1KB CONTIGUOUS per
// channel (2 x float4 per lane) instead of 512B, for better DRAM page
// locality. 10 warps, warp w = row w (8 rows + 2 halo). Per-row mbarrier
// dataflow; conv warps 0..7 process both 128-col halves with their own
// segment weights (zero pad at each tile's col edges incl. the internal
// boundary at col 128).
__global__ void __launch_bounds__(320, 5) fused_kernel(const float* __restrict__ x,
                                                       const float* __restrict__ conv_w,
                                                       const float* __restrict__ conv_b,
                                                       float* __restrict__ out) {
    __shared__ float s[10][256];
    __shared__ __align__(8) unsigned long long mbar[10];

    int bid   = blockIdx.x;
    int strip = bid & 15;         // 16 strips of 8 rows per tile-row-pair
    int pair  = (bid >> 4) & 1;   // which tj pair: cols [pair*256, pair*256+256)
    int ti    = (bid >> 5) & 3;
    int b     = bid >> 7;
    int r0    = strip * 8;
    int tid   = threadIdx.x;

    int w  = tid >> 5;            // warp 0..9 = smem row
    int l  = tid & 31;            // lane
    int gr = r0 - 1 + w;          // row within tile (-1 .. 128)

    // ---- mbarrier init (one per row) ----
    if (tid < 10) mbar_init(smem_u32(&mbar[tid]), 1);
    __syncthreads();

    // ---- Phase 1: channel-L2 for a 256-col row (1KB contiguous per channel) ----
    float a0x = 0.f, a0y = 0.f, a0z = 0.f, a0w = 0.f;   // group l      (cols 4l..)
    float a1x = 0.f, a1y = 0.f, a1z = 0.f, a1w = 0.f;   // group l+32   (cols 128+4l..)
    if ((unsigned)gr < (unsigned)TS) {
        const float4* xp = reinterpret_cast<const float4*>(
            x + (size_t)b * CHW + (size_t)(ti * TS + gr) * Ww + pair * 256);
        #pragma unroll 8
        for (int c = 0; c < Cc; ++c) {
            const float4* xc = xp + (size_t)c * (HW / 4);
            float4 v0 = __ldg(xc + l);
            float4 v1 = __ldg(xc + l + 32);
            a0x = fmaf(v0.x, v0.x, a0x);
            a0y = fmaf(v0.y, v0.y, a0y);
            a0z = fmaf(v0.z, v0.z, a0z);
            a0w = fmaf(v0.w, v0.w, a0w);
            a1x = fmaf(v1.x, v1.x, a1x);
            a1y = fmaf(v1.y, v1.y, a1y);
            a1z = fmaf(v1.z, v1.z, a1z);
            a1w = fmaf(v1.w, v1.w, a1w);
        }
    }
    float4 r0v, r1v;
    r0v.x = sqrtf(a0x); r0v.y = sqrtf(a0y); r0v.z = sqrtf(a0z); r0v.w = sqrtf(a0w);
    r1v.x = sqrtf(a1x); r1v.y = sqrtf(a1y); r1v.z = sqrtf(a1z); r1v.w = sqrtf(a1w);
    *reinterpret_cast<float4*>(&s[w][l * 4])       = r0v;
    *reinterpret_cast<float4*>(&s[w][128 + l * 4]) = r1v;
    __syncwarp();
    if (l == 0) mbar_arrive(smem_u32(&mbar[w]));

    // ---- Phase 2: conv + sigmoid; warp w (w<8) handles output row w, both halves ----
    if (w < 8) {
        // Both halves' weights/biases (ptxas hoists LDGs into the load shadow)
        int seg0 = ti * 4 + pair * 2;
        float wtA[9], wtB[9];
        #pragma unroll
        for (int k = 0; k < 9; ++k) wtA[k] = __ldg(conv_w + seg0 * 9 + k);
        #pragma unroll
        for (int k = 0; k < 9; ++k) wtB[k] = __ldg(conv_w + (seg0 + 1) * 9 + k);
        float biasA = __ldg(conv_b + seg0);
        float biasB = __ldg(conv_b + seg0 + 1);

        mbar_wait_p0(smem_u32(&mbar[w]));
        mbar_wait_p0(smem_u32(&mbar[w + 1]));
        mbar_wait_p0(smem_u32(&mbar[w + 2]));

        #pragma unroll
        for (int half = 0; half < 2; ++half) {
            const float* wt = half ? wtB : wtA;
            float bias = half ? biasB : biasA;
            int cq   = half * 128 + l * 4;        // col within 256-wide smem row
            int lo   = half * 128;                // this tile's left edge
            int hi   = half * 128 + 124;          // this tile's last group start

            float a0 = 0.f, a1 = 0.f, a2 = 0.f, a3 = 0.f;
            #pragma unroll
            for (int dr = 0; dr < 3; ++dr) {
                const float* sr = s[w + dr];
                float4 vc = *reinterpret_cast<const float4*>(&sr[cq]);
                float vm1 = (cq == lo) ? 0.f : sr[cq - 1];
                float vp4 = (cq == hi) ? 0.f : sr[cq + 4];
                float w0 = wt[dr * 3], w1 = wt[dr * 3 + 1], w2 = wt[dr * 3 + 2];
                a0 = fmaf(w0, vm1,  fmaf(w1, vc.x, fmaf(w2, vc.y, a0)));
                a1 = fmaf(w0, vc.x, fmaf(w1, vc.y, fmaf(w2, vc.z, a1)));
                a2 = fmaf(w0, vc.y, fmaf(w1, vc.z, fmaf(w2, vc.w, a2)));
                a3 = fmaf(w0, vc.z, fmaf(w1, vc.w, fmaf(w2, vp4,  a3)));
            }

            float4 o;
            o.x = 1.f / (1.f + __expf(-(a0 + bias)));
            o.y = 1.f / (1.f + __expf(-(a1 + bias)));
            o.z = 1.f / (1.f + __expf(-(a2 + bias)));
            o.w = 1.f / (1.f + __expf(-(a3 + bias)));

            int seg = seg0 + half;
            size_t oofs = (size_t)b * HW + (size_t)seg * (TS * TS)
                        + (size_t)(r0 + w) * TS + l * 4;
            __stwt(reinterpret_cast<float4*>(out + oofs), o);
        }
    }
}

extern "C" void kernel_launch(void* const* d_in, const int* in_sizes, int n_in,
                              void* d_out, int out_size) {
    const float* x  = (const float*)d_in[0];
    const float* cw = (const float*)d_in[1];
    const float* cb = (const float*)d_in[2];
    float* out = (float*)d_out;

    // 16 strips x 2 pairs x 4 ti x 8 batches = 1024 blocks, 320 threads each
    fused_kernel<<<1024, 320>>>(x, cw, cb, out);
}